// round 11
// baseline (speedup 1.0000x reference)
#include <cuda_runtime.h>
#include <cuda_fp16.h>
#include <math.h>

#define NN 50000
#define NE 1600000
#define NB 196             // ceil(NN/256)
#define SCAT_BLOCKS 6250   // ceil(NE/256)
#define QKV_BLOCKS 400

// ---------------- scratch -----------------------------------------------------
__device__ __half d_Qh[NN * 256];       // [n][lane(32)][8ch]  (lane = pair*2+half)
// KV row = 1024B: first 512B = K half-slices ordered by lane, second 512B = V.
__device__ __half d_KV[NN * 512];
__device__ float  d_H[NN * 256];        // skip first, then h (post-ELU); [n][lane][8]
__device__ __half d_HWh[NN * 32];       // h @ Wg, fp16
__device__ float4 d_csr[NE];            // {src(int bits), ax, ay, dis[src]*ay}
__device__ int    d_rank[NE];           // edge's arrival rank within its dst
__device__ int    d_count[NN];          // zeroed for next replay inside scatter_qkv
__device__ int    d_offsets[NN + 1];
__device__ float  d_degw[NN];
__device__ float  d_dis[NN];

__device__ __forceinline__ float ex2f(float x) {
    float y; asm("ex2.approx.f32 %0, %1;" : "=f"(y) : "f"(x)); return y;
}
__device__ __forceinline__ __half2 h2(unsigned u) { return *(__half2*)&u; }

// ---------------- 0: histogram + rank capture ---------------------------------
__global__ void hist_kernel(const int* __restrict__ ei, const float* __restrict__ ea) {
    int e = blockIdx.x * blockDim.x + threadIdx.x;
    if (e < NE) {
        int dst = ei[NE + e];
        d_rank[e] = atomicAdd(&d_count[dst], 1);
        float ay = ((const float2*)ea)[e].y;
        atomicAdd(&d_degw[dst], ay);
    }
}

// ---------------- 1: fused scan + dis -----------------------------------------
__global__ void scan_fused() {
    __shared__ int wsum[8];
    __shared__ int s_carry;
    int tid = threadIdx.x, lane = tid & 31, wid = tid >> 5;
    int b = blockIdx.x;

    int carry = 0;
    for (int i = tid; i < b * 256; i += 256) carry += d_count[i];
    #pragma unroll
    for (int off = 16; off; off >>= 1) carry += __shfl_xor_sync(0xffffffffu, carry, off);
    if (lane == 0) wsum[wid] = carry;
    __syncthreads();
    if (tid == 0) {
        int c = 0;
        #pragma unroll
        for (int i = 0; i < 8; i++) c += wsum[i];
        s_carry = c;
    }
    __syncthreads();

    int i = b * 256 + tid;
    int v = (i < NN) ? d_count[i] : 0;
    int s = v;
    #pragma unroll
    for (int off = 1; off < 32; off <<= 1) {
        int t = __shfl_up_sync(0xffffffffu, s, off);
        if (lane >= off) s += t;
    }
    if (lane == 31) wsum[wid] = s;
    __syncthreads();
    if (tid < 8) {
        int t = wsum[tid];
        #pragma unroll
        for (int off = 1; off < 8; off <<= 1) {
            int u = __shfl_up_sync(0xffu, t, off);
            if (tid >= off) t += u;
        }
        wsum[tid] = t;
    }
    __syncthreads();
    int wexcl = wid ? wsum[wid - 1] : 0;
    if (i < NN) {
        d_offsets[i] = s_carry + wexcl + s - v;
        d_dis[i] = rsqrtf(d_degw[i] + 2.0f);
    }
    if (b == 0 && tid == 0) d_offsets[NN] = NE;
}

// ---------------- 2: fused scatter (no atomics) + qkv -------------------------
__global__ void scatter_qkv_kernel(const int* __restrict__ ei, const float* __restrict__ ea,
                                   const float* __restrict__ x,
                                   const float* __restrict__ Wq, const float* __restrict__ bq,
                                   const float* __restrict__ Wk, const float* __restrict__ bk,
                                   const float* __restrict__ Wv, const float* __restrict__ bv,
                                   const float* __restrict__ Wsk, const float* __restrict__ bsk) {
    int b = blockIdx.x;
    if (b < SCAT_BLOCKS) {
        int e = b * 256 + threadIdx.x;
        if (e < NN) { d_count[e] = 0; d_degw[e] = 0.f; }   // reset for next replay
        if (e < NE) {
            int src = ei[e], dst = ei[NE + e];
            int pos = d_offsets[dst] + d_rank[e];
            float2 a = ((const float2*)ea)[e];
            float4 pk;
            pk.x = __int_as_float(src);
            pk.y = a.x;
            pk.z = a.y;
            pk.w = d_dis[src] * a.y;
            d_csr[pos] = pk;
        }
    } else {
        int lane = threadIdx.x & 31;
        int warp = ((b - SCAT_BLOCKS) * 256 + threadIdx.x) >> 5;
        const int nwarps = QKV_BLOCKS * 8;
        float wq[8], wk[8], wv[8], ws[8];
        #pragma unroll
        for (int i = 0; i < 8; i++) {
            wq[i] = Wq[i * 32 + lane];
            wk[i] = Wk[i * 32 + lane];
            wv[i] = Wv[i * 32 + lane];
            ws[i] = Wsk[i * 32 + lane];
        }
        float bqv = bq[lane], bkv = bk[lane], bvv = bv[lane], bsv = bsk[lane];
        const float QS = 0.25f * 1.4426950408889634f;  // 1/sqrt(16) * log2(e)
        int h = lane >> 4, c = lane & 15;
        int half = c >> 3, j = c & 7;

        for (int n = warp; n < NN; n += nwarps) {
            float x0 = x[n * 64 + lane];
            float x1 = x[n * 64 + 32 + lane];
            #pragma unroll
            for (int bb = 0; bb < 8; bb++) {
                float aq = bqv, ak = bkv, av = bvv, asv = bsv;
                #pragma unroll
                for (int i = 0; i < 8; i++) {
                    const int f = bb * 8 + i;
                    float xv = __shfl_sync(0xffffffffu, (f < 32) ? x0 : x1, f & 31);
                    aq += xv * wq[i]; ak += xv * wk[i]; av += xv * wv[i]; asv += xv * ws[i];
                }
                int pairIdx = bb * 2 + h;
                int vlane = pairIdx * 2 + half;   // owning lane in attn
                d_Qh[n * 256 + vlane * 8 + j] = __float2half(aq * QS);
                d_KV[n * 512 + vlane * 8 + j]       = __float2half(ak);
                d_KV[n * 512 + 256 + vlane * 8 + j] = __float2half(av);
                d_H[n * 256 + vlane * 8 + j] = asv;
            }
        }
    }
}

// ---------------- 3: attention (PROFILED SLOT) --------------------------------
// One warp per dst, whole warp per edge. lane = pair*2 + half owns 8 channels.
__global__ void __launch_bounds__(256, 3) attn_kernel(const float* __restrict__ We) {
    int tid = blockIdx.x * blockDim.x + threadIdx.x;
    int dst = tid >> 5;
    if (dst >= NN) return;
    int lane = threadIdx.x & 31;
    int pair = lane >> 1, half = lane & 1;
    int cbase = ((pair & 1) << 4) + half * 8;   // channel base within HC32

    uint4 qu = ((const uint4*)&d_Qh[dst * 256])[lane];
    __half2 qh[4] = { h2(qu.x), h2(qu.y), h2(qu.z), h2(qu.w) };

    float qw0p = 0.f, qw1p = 0.f;
    #pragma unroll
    for (int i = 0; i < 4; i++) {
        float2 qf = __half22float2(qh[i]);
        qw0p += qf.x * We[cbase + 2 * i]      + qf.y * We[cbase + 2 * i + 1];
        qw1p += qf.x * We[32 + cbase + 2 * i] + qf.y * We[32 + cbase + 2 * i + 1];
    }

    __half2 acch[4];
    #pragma unroll
    for (int i = 0; i < 4; i++) acch[i] = __float2half2_rn(0.f);
    float sax = 0.f, say = 0.f, z = 0.f;

    int start = d_offsets[dst], end = d_offsets[dst + 1];
    for (int e = start; e < end; e += 2) {
        float4 cA = d_csr[e];
        bool hasB = (e + 1 < end);
        float4 cB = d_csr[hasB ? e + 1 : e];
        int srcA = __float_as_int(cA.x);
        int srcB = __float_as_int(cB.x);
        const uint4* bA = (const uint4*)&d_KV[srcA * 512];
        uint4 kaA = bA[lane], vaA = bA[32 + lane];
        const uint4* bB = (const uint4*)&d_KV[srcB * 512];
        uint4 kaB = bB[lane], vaB = bB[32 + lane];

        __half2 dA = __float2half2_rn(0.f);
        dA = __hfma2(qh[0], h2(kaA.x), dA);
        dA = __hfma2(qh[1], h2(kaA.y), dA);
        dA = __hfma2(qh[2], h2(kaA.z), dA);
        dA = __hfma2(qh[3], h2(kaA.w), dA);
        float2 fA = __half22float2(dA);
        float spA = fA.x + fA.y + cA.y * qw0p + cA.z * qw1p;

        __half2 dB = __float2half2_rn(0.f);
        dB = __hfma2(qh[0], h2(kaB.x), dB);
        dB = __hfma2(qh[1], h2(kaB.y), dB);
        dB = __hfma2(qh[2], h2(kaB.z), dB);
        dB = __hfma2(qh[3], h2(kaB.w), dB);
        float2 fB = __half22float2(dB);
        float spB = fB.x + fB.y + cB.y * qw0p + cB.z * qw1p;

        float sA = spA + __shfl_xor_sync(0xffffffffu, spA, 1);
        float sB = spB + __shfl_xor_sync(0xffffffffu, spB, 1);
        float pA = ex2f(sA);
        float pB = hasB ? ex2f(sB) : 0.f;

        z += pA + pB;
        sax = fmaf(pA, cA.y, sax); sax = fmaf(pB, cB.y, sax);
        say = fmaf(pA, cA.z, say); say = fmaf(pB, cB.z, say);

        __half2 pa2 = __float2half2_rn(pA);
        __half2 pb2 = __float2half2_rn(pB);
        acch[0] = __hfma2(pa2, h2(vaA.x), acch[0]);
        acch[1] = __hfma2(pa2, h2(vaA.y), acch[1]);
        acch[2] = __hfma2(pa2, h2(vaA.z), acch[2]);
        acch[3] = __hfma2(pa2, h2(vaA.w), acch[3]);
        acch[0] = __hfma2(pb2, h2(vaB.x), acch[0]);
        acch[1] = __hfma2(pb2, h2(vaB.y), acch[1]);
        acch[2] = __hfma2(pb2, h2(vaB.z), acch[2]);
        acch[3] = __hfma2(pb2, h2(vaB.w), acch[3]);
    }

    float rz = (z > 0.f) ? 1.0f / z : 0.f;
    float f[8];
    #pragma unroll
    for (int i = 0; i < 4; i++) {
        float2 t = __half22float2(acch[i]);
        f[2 * i] = t.x; f[2 * i + 1] = t.y;
    }
    float* Hp = &d_H[dst * 256 + lane * 8];
    float o[8];
    #pragma unroll
    for (int j = 0; j < 8; j++) {
        float w0 = We[cbase + j], w1 = We[32 + cbase + j];
        float a = f[j] + sax * w0 + say * w1;
        float t = fmaf(a, rz, Hp[j]);
        o[j] = (t > 0.f) ? t : 0.1f * (__expf(t) - 1.0f);
    }
    ((float4*)Hp)[0] = make_float4(o[0], o[1], o[2], o[3]);
    ((float4*)Hp)[1] = make_float4(o[4], o[5], o[6], o[7]);
}

// ---------------- 4: hw = h @ Wg, 4 nodes/warp, fp16 out ----------------------
// d_H flat index == Wg row index (verified r9).
__global__ void hw_kernel(const float* __restrict__ Wg) {
    __shared__ float wgs[256 * 32];
    for (int idx = threadIdx.x; idx < 8192; idx += blockDim.x)
        wgs[idx] = Wg[idx];
    __syncthreads();
    int lane = threadIdx.x & 31;
    int warp = (blockIdx.x * blockDim.x + threadIdx.x) >> 5;
    int nwarps = (gridDim.x * blockDim.x) >> 5;
    for (int n0 = warp * 4; n0 < NN; n0 += nwarps * 4) {
        const float4* H0 = (const float4*)&d_H[n0 * 256];
        const float4* H1 = (const float4*)&d_H[(n0 + 1) * 256];
        const float4* H2 = (const float4*)&d_H[(n0 + 2) * 256];
        const float4* H3 = (const float4*)&d_H[(n0 + 3) * 256];
        float a0 = 0.f, a1 = 0.f, a2 = 0.f, a3 = 0.f;
        #pragma unroll 8
        for (int c = 0; c < 64; c++) {
            float w0 = wgs[(4 * c + 0) * 32 + lane];
            float w1 = wgs[(4 * c + 1) * 32 + lane];
            float w2 = wgs[(4 * c + 2) * 32 + lane];
            float w3 = wgs[(4 * c + 3) * 32 + lane];
            float4 h0 = H0[c], h1 = H1[c], h2v = H2[c], h3 = H3[c];
            a0 += h0.x * w0 + h0.y * w1 + h0.z * w2 + h0.w * w3;
            a1 += h1.x * w0 + h1.y * w1 + h1.z * w2 + h1.w * w3;
            a2 += h2v.x * w0 + h2v.y * w1 + h2v.z * w2 + h2v.w * w3;
            a3 += h3.x * w0 + h3.y * w1 + h3.z * w2 + h3.w * w3;
        }
        d_HWh[n0 * 32 + lane] = __float2half(a0);
        d_HWh[(n0 + 1) * 32 + lane] = __float2half(a1);
        d_HWh[(n0 + 2) * 32 + lane] = __float2half(a2);
        d_HWh[(n0 + 3) * 32 + lane] = __float2half(a3);
    }
}

// ---------------- 5: final normalized propagation (fp16 gathers) --------------
__global__ void final_kernel(const float* __restrict__ bg, float* __restrict__ out) {
    int lane = threadIdx.x & 31;
    int dst = (blockIdx.x * blockDim.x + threadIdx.x) >> 5;
    if (dst >= NN) return;
    float dd = d_dis[dst];
    float acc = 2.0f * dd * __half2float(d_HWh[dst * 32 + lane]);  // self loop
    int start = d_offsets[dst], end = d_offsets[dst + 1];
    int last = end - 1;
    for (int t = start; t < end; t += 4) {
        float4 c0 = d_csr[t];
        float4 c1 = d_csr[min(t + 1, last)];
        float4 c2 = d_csr[min(t + 2, last)];
        float4 c3 = d_csr[min(t + 3, last)];
        float w0 = c0.w;
        float w1 = (t + 1 < end) ? c1.w : 0.f;
        float w2 = (t + 2 < end) ? c2.w : 0.f;
        float w3 = (t + 3 < end) ? c3.w : 0.f;
        float v0 = __half2float(d_HWh[__float_as_int(c0.x) * 32 + lane]);
        float v1 = __half2float(d_HWh[__float_as_int(c1.x) * 32 + lane]);
        float v2 = __half2float(d_HWh[__float_as_int(c2.x) * 32 + lane]);
        float v3 = __half2float(d_HWh[__float_as_int(c3.x) * 32 + lane]);
        acc = fmaf(w0, v0, acc);
        acc = fmaf(w1, v1, acc);
        acc = fmaf(w2, v2, acc);
        acc = fmaf(w3, v3, acc);
    }
    out[dst * 32 + lane] = bg[lane] + dd * acc;
}

// ---------------- launch -----------------------------------------------------
extern "C" void kernel_launch(void* const* d_in, const int* in_sizes, int n_in,
                              void* d_out, int out_size) {
    const float* x   = (const float*)d_in[0];
    const float* ea  = (const float*)d_in[1];
    const float* Wq  = (const float*)d_in[2];
    const float* bq  = (const float*)d_in[3];
    const float* Wk  = (const float*)d_in[4];
    const float* bk  = (const float*)d_in[5];
    const float* Wv  = (const float*)d_in[6];
    const float* bv  = (const float*)d_in[7];
    const float* We  = (const float*)d_in[8];
    const float* Wsk = (const float*)d_in[9];
    const float* bsk = (const float*)d_in[10];
    const float* Wg  = (const float*)d_in[11];
    const float* bg  = (const float*)d_in[12];
    const int*   ei  = (const int*)d_in[13];
    float* out = (float*)d_out;

    hist_kernel<<<SCAT_BLOCKS, 256>>>(ei, ea);                       // 0
    scan_fused<<<NB, 256>>>();                                       // 1
    scatter_qkv_kernel<<<SCAT_BLOCKS + QKV_BLOCKS, 256>>>(           // 2
        ei, ea, x, Wq, bq, Wk, bk, Wv, bv, Wsk, bsk);
    attn_kernel<<<(NN * 32 + 255) / 256, 256>>>(We);                 // 3 (profiled)
    hw_kernel<<<296, 256>>>(Wg);                                     // 4
    final_kernel<<<(NN * 32 + 255) / 256, 256>>>(bg, out);           // 5
}

// round 12
// speedup vs baseline: 1.1743x; 1.1743x over previous
#include <cuda_runtime.h>
#include <cuda_fp16.h>
#include <cuda_fp8.h>
#include <math.h>

#define NN 50000
#define NE 1600000
#define NB 196             // ceil(NN/256)
#define SCAT_BLOCKS 6250   // ceil(NE/256)
#define QKV_BLOCKS 400
#define KVROW 768          // 256B K(fp8) + 512B V(fp16)

// ---------------- scratch -----------------------------------------------------
__device__ __half d_Qh[NN * 256];          // [n][lane(32)][8ch]
__device__ unsigned char d_KVb[NN * KVROW]; // row: K fp8 [lane*8], V fp16 at +256 [lane*16]
__device__ float  d_H[NN * 256];           // skip, then h (post-ELU); [n][lane][8]
__device__ __half d_HWh[NN * 32];          // dis[n] * (h @ Wg), fp16
__device__ int2   d_csr[NE];               // {src, half2(ax,ay)}
__device__ int    d_rank[NE];
__device__ int    d_count[NN];
__device__ int    d_offsets[NN + 1];
__device__ float  d_degw[NN];
__device__ float  d_dis[NN];

__device__ __forceinline__ float ex2f(float x) {
    float y; asm("ex2.approx.f32 %0, %1;" : "=f"(y) : "f"(x)); return y;
}
__device__ __forceinline__ __half2 h2(unsigned u) { return *(__half2*)&u; }
__device__ __forceinline__ __half2 fp8x2h2(unsigned short v) {
    __half2_raw r = __nv_cvt_fp8x2_to_halfraw2((__nv_fp8x2_storage_t)v, __NV_E4M3);
    return *(__half2*)&r;
}

// ---------------- 0: histogram + rank capture ---------------------------------
__global__ void hist_kernel(const int* __restrict__ ei, const float* __restrict__ ea) {
    int e = blockIdx.x * blockDim.x + threadIdx.x;
    if (e < NE) {
        int dst = ei[NE + e];
        d_rank[e] = atomicAdd(&d_count[dst], 1);
        atomicAdd(&d_degw[dst], ((const float2*)ea)[e].y);
    }
}

// ---------------- 1: fused scan + dis -----------------------------------------
__global__ void scan_fused() {
    __shared__ int wsum[8];
    __shared__ int s_carry;
    int tid = threadIdx.x, lane = tid & 31, wid = tid >> 5;
    int b = blockIdx.x;

    int carry = 0;
    for (int i = tid; i < b * 256; i += 256) carry += d_count[i];
    #pragma unroll
    for (int off = 16; off; off >>= 1) carry += __shfl_xor_sync(0xffffffffu, carry, off);
    if (lane == 0) wsum[wid] = carry;
    __syncthreads();
    if (tid == 0) {
        int c = 0;
        #pragma unroll
        for (int i = 0; i < 8; i++) c += wsum[i];
        s_carry = c;
    }
    __syncthreads();

    int i = b * 256 + tid;
    int v = (i < NN) ? d_count[i] : 0;
    int s = v;
    #pragma unroll
    for (int off = 1; off < 32; off <<= 1) {
        int t = __shfl_up_sync(0xffffffffu, s, off);
        if (lane >= off) s += t;
    }
    if (lane == 31) wsum[wid] = s;
    __syncthreads();
    if (tid < 8) {
        int t = wsum[tid];
        #pragma unroll
        for (int off = 1; off < 8; off <<= 1) {
            int u = __shfl_up_sync(0xffu, t, off);
            if (tid >= off) t += u;
        }
        wsum[tid] = t;
    }
    __syncthreads();
    int wexcl = wid ? wsum[wid - 1] : 0;
    if (i < NN) {
        d_offsets[i] = s_carry + wexcl + s - v;
        d_dis[i] = rsqrtf(d_degw[i] + 2.0f);
    }
    if (b == 0 && tid == 0) d_offsets[NN] = NE;
}

// ---------------- 2: fused scatter (no atomics, no dis gather) + qkv ----------
__global__ void scatter_qkv_kernel(const int* __restrict__ ei, const float* __restrict__ ea,
                                   const float* __restrict__ x,
                                   const float* __restrict__ Wq, const float* __restrict__ bq,
                                   const float* __restrict__ Wk, const float* __restrict__ bk,
                                   const float* __restrict__ Wv, const float* __restrict__ bv,
                                   const float* __restrict__ Wsk, const float* __restrict__ bsk) {
    int b = blockIdx.x;
    if (b < SCAT_BLOCKS) {
        int e = b * 256 + threadIdx.x;
        if (e < NN) { d_count[e] = 0; d_degw[e] = 0.f; }   // reset for next replay
        if (e < NE) {
            int src = ei[e], dst = ei[NE + e];
            int pos = d_offsets[dst] + d_rank[e];
            float2 a = ((const float2*)ea)[e];
            __half2 a2 = __floats2half2_rn(a.x, a.y);
            int2 pk;
            pk.x = src;
            pk.y = *reinterpret_cast<int*>(&a2);
            d_csr[pos] = pk;
        }
    } else {
        int lane = threadIdx.x & 31;
        int warp = ((b - SCAT_BLOCKS) * 256 + threadIdx.x) >> 5;
        const int nwarps = QKV_BLOCKS * 8;
        float wq[8], wk[8], wv[8], ws[8];
        #pragma unroll
        for (int i = 0; i < 8; i++) {
            wq[i] = Wq[i * 32 + lane];
            wk[i] = Wk[i * 32 + lane];
            wv[i] = Wv[i * 32 + lane];
            ws[i] = Wsk[i * 32 + lane];
        }
        float bqv = bq[lane], bkv = bk[lane], bvv = bv[lane], bsv = bsk[lane];
        const float QS = 0.25f * 1.4426950408889634f;  // 1/sqrt(16) * log2(e)
        int h = lane >> 4, c = lane & 15;
        int half = c >> 3, j = c & 7;

        for (int n = warp; n < NN; n += nwarps) {
            float x0 = x[n * 64 + lane];
            float x1 = x[n * 64 + 32 + lane];
            #pragma unroll
            for (int bb = 0; bb < 8; bb++) {
                float aq = bqv, ak = bkv, av = bvv, asv = bsv;
                #pragma unroll
                for (int i = 0; i < 8; i++) {
                    const int f = bb * 8 + i;
                    float xv = __shfl_sync(0xffffffffu, (f < 32) ? x0 : x1, f & 31);
                    aq += xv * wq[i]; ak += xv * wk[i]; av += xv * wv[i]; asv += xv * ws[i];
                }
                int pairIdx = bb * 2 + h;
                int vlane = pairIdx * 2 + half;
                d_Qh[n * 256 + vlane * 8 + j] = __float2half(aq * QS);
                d_KVb[n * KVROW + vlane * 8 + j] =
                    __nv_cvt_float_to_fp8(ak, __NV_SATFINITE, __NV_E4M3);
                ((__half*)(d_KVb + n * KVROW + 256))[vlane * 8 + j] = __float2half(av);
                d_H[n * 256 + vlane * 8 + j] = asv;
            }
        }
    }
}

// ---------------- 3: attention (PROFILED SLOT) --------------------------------
// One warp per dst, whole warp per edge; K fp8 (8B/lane), V fp16 (16B/lane).
__global__ void __launch_bounds__(256, 3) attn_kernel(const float* __restrict__ We) {
    int tid = blockIdx.x * blockDim.x + threadIdx.x;
    int dst = tid >> 5;
    if (dst >= NN) return;
    int lane = threadIdx.x & 31;
    int pair = lane >> 1, half = lane & 1;
    int cbase = ((pair & 1) << 4) + half * 8;

    uint4 qu = ((const uint4*)&d_Qh[dst * 256])[lane];
    __half2 qh[4] = { h2(qu.x), h2(qu.y), h2(qu.z), h2(qu.w) };

    float qw0p = 0.f, qw1p = 0.f;
    #pragma unroll
    for (int i = 0; i < 4; i++) {
        float2 qf = __half22float2(qh[i]);
        qw0p += qf.x * We[cbase + 2 * i]      + qf.y * We[cbase + 2 * i + 1];
        qw1p += qf.x * We[32 + cbase + 2 * i] + qf.y * We[32 + cbase + 2 * i + 1];
    }

    __half2 acch[4];
    #pragma unroll
    for (int i = 0; i < 4; i++) acch[i] = __float2half2_rn(0.f);
    float sax = 0.f, say = 0.f, z = 0.f;

    int start = d_offsets[dst], end = d_offsets[dst + 1];
    for (int e = start; e < end; e += 2) {
        int2 cA = d_csr[e];
        bool hasB = (e + 1 < end);
        int2 cB = d_csr[hasB ? e + 1 : e];
        float2 aA = __half22float2(h2((unsigned)cA.y));
        float2 aB = __half22float2(h2((unsigned)cB.y));
        const unsigned char* bA = d_KVb + cA.x * KVROW;
        const unsigned char* bB = d_KVb + cB.x * KVROW;
        uint2 kuA = ((const uint2*)bA)[lane];
        uint4 vaA = ((const uint4*)(bA + 256))[lane];
        uint2 kuB = ((const uint2*)bB)[lane];
        uint4 vaB = ((const uint4*)(bB + 256))[lane];

        __half2 dA = __float2half2_rn(0.f);
        dA = __hfma2(qh[0], fp8x2h2((unsigned short)(kuA.x & 0xffffu)), dA);
        dA = __hfma2(qh[1], fp8x2h2((unsigned short)(kuA.x >> 16)), dA);
        dA = __hfma2(qh[2], fp8x2h2((unsigned short)(kuA.y & 0xffffu)), dA);
        dA = __hfma2(qh[3], fp8x2h2((unsigned short)(kuA.y >> 16)), dA);
        float2 fA = __half22float2(dA);
        float spA = fA.x + fA.y + aA.x * qw0p + aA.y * qw1p;

        __half2 dB = __float2half2_rn(0.f);
        dB = __hfma2(qh[0], fp8x2h2((unsigned short)(kuB.x & 0xffffu)), dB);
        dB = __hfma2(qh[1], fp8x2h2((unsigned short)(kuB.x >> 16)), dB);
        dB = __hfma2(qh[2], fp8x2h2((unsigned short)(kuB.y & 0xffffu)), dB);
        dB = __hfma2(qh[3], fp8x2h2((unsigned short)(kuB.y >> 16)), dB);
        float2 fB = __half22float2(dB);
        float spB = fB.x + fB.y + aB.x * qw0p + aB.y * qw1p;

        float sA = spA + __shfl_xor_sync(0xffffffffu, spA, 1);
        float sB = spB + __shfl_xor_sync(0xffffffffu, spB, 1);
        float pA = ex2f(sA);
        float pB = hasB ? ex2f(sB) : 0.f;

        z += pA + pB;
        sax = fmaf(pA, aA.x, sax); sax = fmaf(pB, aB.x, sax);
        say = fmaf(pA, aA.y, say); say = fmaf(pB, aB.y, say);

        __half2 pa2 = __float2half2_rn(pA);
        __half2 pb2 = __float2half2_rn(pB);
        acch[0] = __hfma2(pa2, h2(vaA.x), acch[0]);
        acch[1] = __hfma2(pa2, h2(vaA.y), acch[1]);
        acch[2] = __hfma2(pa2, h2(vaA.z), acch[2]);
        acch[3] = __hfma2(pa2, h2(vaA.w), acch[3]);
        acch[0] = __hfma2(pb2, h2(vaB.x), acch[0]);
        acch[1] = __hfma2(pb2, h2(vaB.y), acch[1]);
        acch[2] = __hfma2(pb2, h2(vaB.z), acch[2]);
        acch[3] = __hfma2(pb2, h2(vaB.w), acch[3]);
    }

    float rz = (z > 0.f) ? 1.0f / z : 0.f;
    float f[8];
    #pragma unroll
    for (int i = 0; i < 4; i++) {
        float2 t = __half22float2(acch[i]);
        f[2 * i] = t.x; f[2 * i + 1] = t.y;
    }
    float* Hp = &d_H[dst * 256 + lane * 8];
    float o[8];
    #pragma unroll
    for (int j = 0; j < 8; j++) {
        float w0 = We[cbase + j], w1 = We[32 + cbase + j];
        float a = f[j] + sax * w0 + say * w1;
        float t = fmaf(a, rz, Hp[j]);
        o[j] = (t > 0.f) ? t : 0.1f * (__expf(t) - 1.0f);
    }
    ((float4*)Hp)[0] = make_float4(o[0], o[1], o[2], o[3]);
    ((float4*)Hp)[1] = make_float4(o[4], o[5], o[6], o[7]);
}

// ---------------- 4: hw = dis * (h @ Wg), 4 nodes/warp, fp16 out --------------
__global__ void hw_kernel(const float* __restrict__ Wg) {
    __shared__ float wgs[256 * 32];
    for (int idx = threadIdx.x; idx < 8192; idx += blockDim.x)
        wgs[idx] = Wg[idx];
    __syncthreads();
    int lane = threadIdx.x & 31;
    int warp = (blockIdx.x * blockDim.x + threadIdx.x) >> 5;
    int nwarps = (gridDim.x * blockDim.x) >> 5;
    for (int n0 = warp * 4; n0 < NN; n0 += nwarps * 4) {
        const float4* H0 = (const float4*)&d_H[n0 * 256];
        const float4* H1 = (const float4*)&d_H[(n0 + 1) * 256];
        const float4* H2 = (const float4*)&d_H[(n0 + 2) * 256];
        const float4* H3 = (const float4*)&d_H[(n0 + 3) * 256];
        float a0 = 0.f, a1 = 0.f, a2 = 0.f, a3 = 0.f;
        #pragma unroll 8
        for (int c = 0; c < 64; c++) {
            float w0 = wgs[(4 * c + 0) * 32 + lane];
            float w1 = wgs[(4 * c + 1) * 32 + lane];
            float w2 = wgs[(4 * c + 2) * 32 + lane];
            float w3 = wgs[(4 * c + 3) * 32 + lane];
            float4 h0 = H0[c], h1 = H1[c], h2v = H2[c], h3 = H3[c];
            a0 += h0.x * w0 + h0.y * w1 + h0.z * w2 + h0.w * w3;
            a1 += h1.x * w0 + h1.y * w1 + h1.z * w2 + h1.w * w3;
            a2 += h2v.x * w0 + h2v.y * w1 + h2v.z * w2 + h2v.w * w3;
            a3 += h3.x * w0 + h3.y * w1 + h3.z * w2 + h3.w * w3;
        }
        d_HWh[n0 * 32 + lane]       = __float2half(d_dis[n0] * a0);
        d_HWh[(n0 + 1) * 32 + lane] = __float2half(d_dis[n0 + 1] * a1);
        d_HWh[(n0 + 2) * 32 + lane] = __float2half(d_dis[n0 + 2] * a2);
        d_HWh[(n0 + 3) * 32 + lane] = __float2half(d_dis[n0 + 3] * a3);
    }
}

// ---------------- 5: final normalized propagation -----------------------------
// out = bg + dis[dst] * ( sum_e ay_e * HW'[src_e] + 2 * HW'[dst] ),  HW' = dis*hw
__global__ void final_kernel(const float* __restrict__ bg, float* __restrict__ out) {
    int lane = threadIdx.x & 31;
    int dst = (blockIdx.x * blockDim.x + threadIdx.x) >> 5;
    if (dst >= NN) return;
    float dd = d_dis[dst];
    float acc = 2.0f * __half2float(d_HWh[dst * 32 + lane]);
    int start = d_offsets[dst], end = d_offsets[dst + 1];
    int last = end - 1;
    for (int t = start; t < end; t += 4) {
        int2 c0 = d_csr[t];
        int2 c1 = d_csr[min(t + 1, last)];
        int2 c2 = d_csr[min(t + 2, last)];
        int2 c3 = d_csr[min(t + 3, last)];
        float w0 = __half22float2(h2((unsigned)c0.y)).y;
        float w1 = (t + 1 < end) ? __half22float2(h2((unsigned)c1.y)).y : 0.f;
        float w2 = (t + 2 < end) ? __half22float2(h2((unsigned)c2.y)).y : 0.f;
        float w3 = (t + 3 < end) ? __half22float2(h2((unsigned)c3.y)).y : 0.f;
        float v0 = __half2float(d_HWh[c0.x * 32 + lane]);
        float v1 = __half2float(d_HWh[c1.x * 32 + lane]);
        float v2 = __half2float(d_HWh[c2.x * 32 + lane]);
        float v3 = __half2float(d_HWh[c3.x * 32 + lane]);
        acc = fmaf(w0, v0, acc);
        acc = fmaf(w1, v1, acc);
        acc = fmaf(w2, v2, acc);
        acc = fmaf(w3, v3, acc);
    }
    out[dst * 32 + lane] = bg[lane] + dd * acc;
}

// ---------------- launch -----------------------------------------------------
extern "C" void kernel_launch(void* const* d_in, const int* in_sizes, int n_in,
                              void* d_out, int out_size) {
    const float* x   = (const float*)d_in[0];
    const float* ea  = (const float*)d_in[1];
    const float* Wq  = (const float*)d_in[2];
    const float* bq  = (const float*)d_in[3];
    const float* Wk  = (const float*)d_in[4];
    const float* bk  = (const float*)d_in[5];
    const float* Wv  = (const float*)d_in[6];
    const float* bv  = (const float*)d_in[7];
    const float* We  = (const float*)d_in[8];
    const float* Wsk = (const float*)d_in[9];
    const float* bsk = (const float*)d_in[10];
    const float* Wg  = (const float*)d_in[11];
    const float* bg  = (const float*)d_in[12];
    const int*   ei  = (const int*)d_in[13];
    float* out = (float*)d_out;

    hist_kernel<<<SCAT_BLOCKS, 256>>>(ei, ea);                       // 0
    scan_fused<<<NB, 256>>>();                                       // 1
    scatter_qkv_kernel<<<SCAT_BLOCKS + QKV_BLOCKS, 256>>>(           // 2
        ei, ea, x, Wq, bq, Wk, bk, Wv, bv, Wsk, bsk);
    attn_kernel<<<(NN * 32 + 255) / 256, 256>>>(We);                 // 3 (profiled)
    hw_kernel<<<296, 256>>>(Wg);                                     // 4
    final_kernel<<<(NN * 32 + 255) / 256, 256>>>(bg, out);           // 5
}

// round 14
// speedup vs baseline: 1.2534x; 1.0673x over previous
#include <cuda_runtime.h>
#include <cuda_fp16.h>
#include <cuda_fp8.h>
#include <math.h>

#define NN 50000
#define NE 1600000
#define NB 196             // ceil(NN/256)
#define SCAT_BLOCKS 6250   // ceil(NE/256)
#define QKV_BLOCKS 400
#define KVROW 768          // 256B K(fp8) + 512B V(fp16)

// ---------------- scratch -----------------------------------------------------
__device__ __half d_Qh[NN * 256];          // [n][lane(32)][8ch]
__device__ unsigned char d_KVb[NN * KVROW]; // K fp8 [lane*8], V fp16 at +256
__device__ float  d_H[NN * 256];           // skip, then h (post-ELU)
__device__ __half d_HWh[NN * 32];          // dis[n] * (h @ Wg), fp16
__device__ int2   d_csr[NE];               // {src, half2(ax,ay)}
__device__ int    d_rank[NE];
__device__ unsigned long long d_pack[NN];  // count<<40 | sum(ay * 2^20)
__device__ int    d_offsets[NN + 1];
__device__ float  d_dis[NN];

__device__ __forceinline__ float ex2f(float x) {
    float y; asm("ex2.approx.f32 %0, %1;" : "=f"(y) : "f"(x)); return y;
}
__device__ __forceinline__ __half2 h2(unsigned u) { return *(__half2*)&u; }
__device__ __forceinline__ __half2 fp8x2h2(unsigned short v) {
    __half2_raw r = __nv_cvt_fp8x2_to_halfraw2((__nv_fp8x2_storage_t)v, __NV_E4M3);
    return *(__half2*)&r;
}

// ---------------- 0: histogram — ONE packed atomic per edge -------------------
__global__ void hist_kernel(const int* __restrict__ ei, const float* __restrict__ ea) {
    int e = blockIdx.x * blockDim.x + threadIdx.x;
    if (e < NE) {
        int dst = ei[NE + e];
        float ay = ((const float2*)ea)[e].y;
        unsigned long long add = (1ULL << 40) +
            (unsigned long long)__float2uint_rn(ay * 1048576.0f);
        unsigned long long ret = atomicAdd(&d_pack[dst], add);
        d_rank[e] = (int)(ret >> 40);
    }
}

// ---------------- 1: fused scan + dis -----------------------------------------
__global__ void scan_fused() {
    __shared__ int wsum[8];
    __shared__ int s_carry;
    int tid = threadIdx.x, lane = tid & 31, wid = tid >> 5;
    int b = blockIdx.x;

    int carry = 0;
    for (int i = tid; i < b * 256; i += 256) carry += (int)(d_pack[i] >> 40);
    #pragma unroll
    for (int off = 16; off; off >>= 1) carry += __shfl_xor_sync(0xffffffffu, carry, off);
    if (lane == 0) wsum[wid] = carry;
    __syncthreads();
    if (tid == 0) {
        int c = 0;
        #pragma unroll
        for (int i = 0; i < 8; i++) c += wsum[i];
        s_carry = c;
    }
    __syncthreads();

    int i = b * 256 + tid;
    unsigned long long pk = (i < NN) ? d_pack[i] : 0ULL;
    int v = (int)(pk >> 40);
    int s = v;
    #pragma unroll
    for (int off = 1; off < 32; off <<= 1) {
        int t = __shfl_up_sync(0xffffffffu, s, off);
        if (lane >= off) s += t;
    }
    if (lane == 31) wsum[wid] = s;
    __syncthreads();
    if (tid < 8) {
        int t = wsum[tid];
        #pragma unroll
        for (int off = 1; off < 8; off <<= 1) {
            int u = __shfl_up_sync(0xffu, t, off);
            if (tid >= off) t += u;
        }
        wsum[tid] = t;
    }
    __syncthreads();
    int wexcl = wid ? wsum[wid - 1] : 0;
    if (i < NN) {
        d_offsets[i] = s_carry + wexcl + s - v;
        float degw = (float)(pk & ((1ULL << 40) - 1)) * (1.0f / 1048576.0f);
        d_dis[i] = rsqrtf(degw + 2.0f);
    }
    if (b == 0 && tid == 0) d_offsets[NN] = NE;
}

// ---------------- 2: fused scatter (no atomics) + qkv -------------------------
__global__ void scatter_qkv_kernel(const int* __restrict__ ei, const float* __restrict__ ea,
                                   const float* __restrict__ x,
                                   const float* __restrict__ Wq, const float* __restrict__ bq,
                                   const float* __restrict__ Wk, const float* __restrict__ bk,
                                   const float* __restrict__ Wv, const float* __restrict__ bv,
                                   const float* __restrict__ Wsk, const float* __restrict__ bsk) {
    int b = blockIdx.x;
    if (b < SCAT_BLOCKS) {
        int e = b * 256 + threadIdx.x;
        if (e < NN) d_pack[e] = 0ULL;   // reset for next replay
        if (e < NE) {
            int src = ei[e], dst = ei[NE + e];
            int pos = d_offsets[dst] + d_rank[e];
            float2 a = ((const float2*)ea)[e];
            __half2 a2 = __floats2half2_rn(a.x, a.y);
            int2 pk;
            pk.x = src;
            pk.y = *reinterpret_cast<int*>(&a2);
            d_csr[pos] = pk;
        }
    } else {
        int lane = threadIdx.x & 31;
        int warp = ((b - SCAT_BLOCKS) * 256 + threadIdx.x) >> 5;
        const int nwarps = QKV_BLOCKS * 8;
        float wq[8], wk[8], wv[8], ws[8];
        #pragma unroll
        for (int i = 0; i < 8; i++) {
            wq[i] = Wq[i * 32 + lane];
            wk[i] = Wk[i * 32 + lane];
            wv[i] = Wv[i * 32 + lane];
            ws[i] = Wsk[i * 32 + lane];
        }
        float bqv = bq[lane], bkv = bk[lane], bvv = bv[lane], bsv = bsk[lane];
        const float QS = 0.25f * 1.4426950408889634f;
        int h = lane >> 4, c = lane & 15;
        int half = c >> 3, j = c & 7;

        for (int n = warp; n < NN; n += nwarps) {
            float x0 = x[n * 64 + lane];
            float x1 = x[n * 64 + 32 + lane];
            #pragma unroll
            for (int bb = 0; bb < 8; bb++) {
                float aq = bqv, ak = bkv, av = bvv, asv = bsv;
                #pragma unroll
                for (int i = 0; i < 8; i++) {
                    const int f = bb * 8 + i;
                    float xv = __shfl_sync(0xffffffffu, (f < 32) ? x0 : x1, f & 31);
                    aq += xv * wq[i]; ak += xv * wk[i]; av += xv * wv[i]; asv += xv * ws[i];
                }
                int pairIdx = bb * 2 + h;
                int vlane = pairIdx * 2 + half;
                d_Qh[n * 256 + vlane * 8 + j] = __float2half(aq * QS);
                d_KVb[n * KVROW + vlane * 8 + j] =
                    __nv_cvt_float_to_fp8(ak, __NV_SATFINITE, __NV_E4M3);
                ((__half*)(d_KVb + n * KVROW + 256))[vlane * 8 + j] = __float2half(av);
                d_H[n * 256 + vlane * 8 + j] = asv;
            }
        }
    }
}

// ---------------- 3: attention (PROFILED SLOT) --------------------------------
__global__ void __launch_bounds__(256, 4) attn_kernel(const float* __restrict__ We) {
    int tid = blockIdx.x * blockDim.x + threadIdx.x;
    int dst = tid >> 5;
    if (dst >= NN) return;
    int lane = threadIdx.x & 31;
    int pair = lane >> 1, half = lane & 1;
    int cbase = ((pair & 1) << 4) + half * 8;

    uint4 qu = ((const uint4*)&d_Qh[dst * 256])[lane];
    __half2 qh[4] = { h2(qu.x), h2(qu.y), h2(qu.z), h2(qu.w) };

    float qw0p = 0.f, qw1p = 0.f;
    #pragma unroll
    for (int i = 0; i < 4; i++) {
        float2 qf = __half22float2(qh[i]);
        qw0p += qf.x * We[cbase + 2 * i]      + qf.y * We[cbase + 2 * i + 1];
        qw1p += qf.x * We[32 + cbase + 2 * i] + qf.y * We[32 + cbase + 2 * i + 1];
    }

    __half2 acch[4];
    #pragma unroll
    for (int i = 0; i < 4; i++) acch[i] = __float2half2_rn(0.f);
    float sax = 0.f, say = 0.f, z = 0.f;

    int start = d_offsets[dst], end = d_offsets[dst + 1];
    for (int e = start; e < end; e += 2) {
        int2 cA = d_csr[e];
        bool hasB = (e + 1 < end);
        int2 cB = d_csr[hasB ? e + 1 : e];
        float2 aA = __half22float2(h2((unsigned)cA.y));
        float2 aB = __half22float2(h2((unsigned)cB.y));
        const unsigned char* bA = d_KVb + cA.x * KVROW;
        const unsigned char* bB = d_KVb + cB.x * KVROW;
        uint2 kuA = ((const uint2*)bA)[lane];
        uint4 vaA = ((const uint4*)(bA + 256))[lane];
        uint2 kuB = ((const uint2*)bB)[lane];
        uint4 vaB = ((const uint4*)(bB + 256))[lane];

        __half2 dA = __float2half2_rn(0.f);
        dA = __hfma2(qh[0], fp8x2h2((unsigned short)(kuA.x & 0xffffu)), dA);
        dA = __hfma2(qh[1], fp8x2h2((unsigned short)(kuA.x >> 16)), dA);
        dA = __hfma2(qh[2], fp8x2h2((unsigned short)(kuA.y & 0xffffu)), dA);
        dA = __hfma2(qh[3], fp8x2h2((unsigned short)(kuA.y >> 16)), dA);
        float2 fA = __half22float2(dA);
        float spA = fA.x + fA.y + aA.x * qw0p + aA.y * qw1p;

        __half2 dB = __float2half2_rn(0.f);
        dB = __hfma2(qh[0], fp8x2h2((unsigned short)(kuB.x & 0xffffu)), dB);
        dB = __hfma2(qh[1], fp8x2h2((unsigned short)(kuB.x >> 16)), dB);
        dB = __hfma2(qh[2], fp8x2h2((unsigned short)(kuB.y & 0xffffu)), dB);
        dB = __hfma2(qh[3], fp8x2h2((unsigned short)(kuB.y >> 16)), dB);
        float2 fB = __half22float2(dB);
        float spB = fB.x + fB.y + aB.x * qw0p + aB.y * qw1p;

        float sA = spA + __shfl_xor_sync(0xffffffffu, spA, 1);
        float sB = spB + __shfl_xor_sync(0xffffffffu, spB, 1);
        float pA = ex2f(sA);
        float pB = hasB ? ex2f(sB) : 0.f;

        z += pA + pB;
        sax = fmaf(pA, aA.x, sax); sax = fmaf(pB, aB.x, sax);
        say = fmaf(pA, aA.y, say); say = fmaf(pB, aB.y, say);

        __half2 pa2 = __float2half2_rn(pA);
        __half2 pb2 = __float2half2_rn(pB);
        acch[0] = __hfma2(pa2, h2(vaA.x), acch[0]);
        acch[1] = __hfma2(pa2, h2(vaA.y), acch[1]);
        acch[2] = __hfma2(pa2, h2(vaA.z), acch[2]);
        acch[3] = __hfma2(pa2, h2(vaA.w), acch[3]);
        acch[0] = __hfma2(pb2, h2(vaB.x), acch[0]);
        acch[1] = __hfma2(pb2, h2(vaB.y), acch[1]);
        acch[2] = __hfma2(pb2, h2(vaB.z), acch[2]);
        acch[3] = __hfma2(pb2, h2(vaB.w), acch[3]);
    }

    float rz = (z > 0.f) ? 1.0f / z : 0.f;
    float f[8];
    #pragma unroll
    for (int i = 0; i < 4; i++) {
        float2 t = __half22float2(acch[i]);
        f[2 * i] = t.x; f[2 * i + 1] = t.y;
    }
    float* Hp = &d_H[dst * 256 + lane * 8];
    float o[8];
    #pragma unroll
    for (int j = 0; j < 8; j++) {
        float w0 = We[cbase + j], w1 = We[32 + cbase + j];
        float a = f[j] + sax * w0 + say * w1;
        float t = fmaf(a, rz, Hp[j]);
        o[j] = (t > 0.f) ? t : 0.1f * (__expf(t) - 1.0f);
    }
    ((float4*)Hp)[0] = make_float4(o[0], o[1], o[2], o[3]);
    ((float4*)Hp)[1] = make_float4(o[4], o[5], o[6], o[7]);
}

// ---------------- 4: hw = dis * (h @ Wg), 4 nodes/warp, fp16 out --------------
__global__ void hw_kernel(const float* __restrict__ Wg) {
    __shared__ float wgs[256 * 32];
    for (int idx = threadIdx.x; idx < 8192; idx += blockDim.x)
        wgs[idx] = Wg[idx];
    __syncthreads();
    int lane = threadIdx.x & 31;
    int warp = (blockIdx.x * blockDim.x + threadIdx.x) >> 5;
    int nwarps = (gridDim.x * blockDim.x) >> 5;
    for (int n0 = warp * 4; n0 < NN; n0 += nwarps * 4) {
        const float4* H0 = (const float4*)&d_H[n0 * 256];
        const float4* H1 = (const float4*)&d_H[(n0 + 1) * 256];
        const float4* H2 = (const float4*)&d_H[(n0 + 2) * 256];
        const float4* H3 = (const float4*)&d_H[(n0 + 3) * 256];
        float a0 = 0.f, a1 = 0.f, a2 = 0.f, a3 = 0.f;
        #pragma unroll 8
        for (int c = 0; c < 64; c++) {
            float w0 = wgs[(4 * c + 0) * 32 + lane];
            float w1 = wgs[(4 * c + 1) * 32 + lane];
            float w2 = wgs[(4 * c + 2) * 32 + lane];
            float w3 = wgs[(4 * c + 3) * 32 + lane];
            float4 h0 = H0[c], h1 = H1[c], h2v = H2[c], h3 = H3[c];
            a0 += h0.x * w0 + h0.y * w1 + h0.z * w2 + h0.w * w3;
            a1 += h1.x * w0 + h1.y * w1 + h1.z * w2 + h1.w * w3;
            a2 += h2v.x * w0 + h2v.y * w1 + h2v.z * w2 + h2v.w * w3;
            a3 += h3.x * w0 + h3.y * w1 + h3.z * w2 + h3.w * w3;
        }
        d_HWh[n0 * 32 + lane]       = __float2half(d_dis[n0] * a0);
        d_HWh[(n0 + 1) * 32 + lane] = __float2half(d_dis[n0 + 1] * a1);
        d_HWh[(n0 + 2) * 32 + lane] = __float2half(d_dis[n0 + 2] * a2);
        d_HWh[(n0 + 3) * 32 + lane] = __float2half(d_dis[n0 + 3] * a3);
    }
}

// ---------------- 5: final normalized propagation -----------------------------
__global__ void final_kernel(const float* __restrict__ bg, float* __restrict__ out) {
    int lane = threadIdx.x & 31;
    int dst = (blockIdx.x * blockDim.x + threadIdx.x) >> 5;
    if (dst >= NN) return;
    float dd = d_dis[dst];
    float acc = 2.0f * __half2float(d_HWh[dst * 32 + lane]);
    int start = d_offsets[dst], end = d_offsets[dst + 1];
    int last = end - 1;
    for (int t = start; t < end; t += 4) {
        int2 c0 = d_csr[t];
        int2 c1 = d_csr[min(t + 1, last)];
        int2 c2 = d_csr[min(t + 2, last)];
        int2 c3 = d_csr[min(t + 3, last)];
        float w0 = __half22float2(h2((unsigned)c0.y)).y;
        float w1 = (t + 1 < end) ? __half22float2(h2((unsigned)c1.y)).y : 0.f;
        float w2 = (t + 2 < end) ? __half22float2(h2((unsigned)c2.y)).y : 0.f;
        float w3 = (t + 3 < end) ? __half22float2(h2((unsigned)c3.y)).y : 0.f;
        float v0 = __half2float(d_HWh[c0.x * 32 + lane]);
        float v1 = __half2float(d_HWh[c1.x * 32 + lane]);
        float v2 = __half2float(d_HWh[c2.x * 32 + lane]);
        float v3 = __half2float(d_HWh[c3.x * 32 + lane]);
        acc = fmaf(w0, v0, acc);
        acc = fmaf(w1, v1, acc);
        acc = fmaf(w2, v2, acc);
        acc = fmaf(w3, v3, acc);
    }
    out[dst * 32 + lane] = bg[lane] + dd * acc;
}

// ---------------- launch -----------------------------------------------------
extern "C" void kernel_launch(void* const* d_in, const int* in_sizes, int n_in,
                              void* d_out, int out_size) {
    const float* x   = (const float*)d_in[0];
    const float* ea  = (const float*)d_in[1];
    const float* Wq  = (const float*)d_in[2];
    const float* bq  = (const float*)d_in[3];
    const float* Wk  = (const float*)d_in[4];
    const float* bk  = (const float*)d_in[5];
    const float* Wv  = (const float*)d_in[6];
    const float* bv  = (const float*)d_in[7];
    const float* We  = (const float*)d_in[8];
    const float* Wsk = (const float*)d_in[9];
    const float* bsk = (const float*)d_in[10];
    const float* Wg  = (const float*)d_in[11];
    const float* bg  = (const float*)d_in[12];
    const int*   ei  = (const int*)d_in[13];
    float* out = (float*)d_out;

    hist_kernel<<<SCAT_BLOCKS, 256>>>(ei, ea);                       // 0
    scan_fused<<<NB, 256>>>();                                       // 1
    scatter_qkv_kernel<<<SCAT_BLOCKS + QKV_BLOCKS, 256>>>(           // 2
        ei, ea, x, Wq, bq, Wk, bk, Wv, bv, Wsk, bsk);
    attn_kernel<<<(NN * 32 + 255) / 256, 256>>>(We);                 // 3 (profiled)
    hw_kernel<<<296, 256>>>(Wg);                                     // 4
    final_kernel<<<(NN * 32 + 255) / 256, 256>>>(bg, out);           // 5
}